// round 5
// baseline (speedup 1.0000x reference)
#include <cuda_runtime.h>
#include <cuda_fp16.h>
#include <math.h>

#define NN 200000
#define NE 6400000
#define NG 64
#define NB_SCAN 782   // ceil(NN/256)

// ---- device scratch (static, no runtime allocation) ----
__device__ int    g_count[NN];        // in-degree (histogram)
__device__ int    g_cursor[NN];       // scatter cursor
__device__ int    g_off[NN];          // CSR offsets (exclusive scan)
__device__ int    g_bsum[1024];       // scan block totals
__device__ int    g_scan_done;        // scan sync counter
__device__ int    g_srcs[NE];         // src ids sorted by dst (25.6MB, L2-resident)
__device__ float  g_efsum[NN * 4];    // per-dst edge-feature sums (4MB, L2-resident)
__device__ float  g_nf8[NN * 8];      // node_feat padded to 8 floats/row
__device__ __half g_h1h[NN * 32];     // layer-1 output (fp16, 12.8MB)
__device__ float  g_pooled[NG * 32];

// ---------------- setup: zero scratch + pad node features ----------------
__global__ void setup_kernel(const float* __restrict__ node_feat) {
    int i = blockIdx.x * blockDim.x + threadIdx.x;
    if (i < NN * 8) {
        int n = i >> 3, k = i & 7;
        g_nf8[i] = (k < 7) ? node_feat[n * 7 + k] : 0.0f;
    }
    if (i < NN * 4) g_efsum[i] = 0.0f;
    if (i < NN) { g_count[i] = 0; g_cursor[i] = 0; }
    if (i < NG * 32) g_pooled[i] = 0.0f;
    if (i == 0) g_scan_done = 0;
}

// ---------------- fused histogram + edge-feature segment-sum ----------------
// 4 edges per thread; all atomics land in L2-resident tables.
__global__ void histsum_kernel(const int4* __restrict__ dst4,
                               const float4* __restrict__ ef4) {
    int i = blockIdx.x * blockDim.x + threadIdx.x;
    if (i >= NE / 4) return;
    int4 d = dst4[i];
    float4 e0 = ef4[i * 4 + 0];
    float4 e1 = ef4[i * 4 + 1];
    float4 e2 = ef4[i * 4 + 2];
    float4 e3 = ef4[i * 4 + 3];

    atomicAdd(&g_count[d.x], 1);
    atomicAdd(&g_efsum[d.x * 4 + 0], e0.x);
    atomicAdd(&g_efsum[d.x * 4 + 1], e0.y);
    atomicAdd(&g_efsum[d.x * 4 + 2], e0.z);
    atomicAdd(&g_efsum[d.x * 4 + 3], e0.w);

    atomicAdd(&g_count[d.y], 1);
    atomicAdd(&g_efsum[d.y * 4 + 0], e1.x);
    atomicAdd(&g_efsum[d.y * 4 + 1], e1.y);
    atomicAdd(&g_efsum[d.y * 4 + 2], e1.z);
    atomicAdd(&g_efsum[d.y * 4 + 3], e1.w);

    atomicAdd(&g_count[d.z], 1);
    atomicAdd(&g_efsum[d.z * 4 + 0], e2.x);
    atomicAdd(&g_efsum[d.z * 4 + 1], e2.y);
    atomicAdd(&g_efsum[d.z * 4 + 2], e2.z);
    atomicAdd(&g_efsum[d.z * 4 + 3], e2.w);

    atomicAdd(&g_count[d.w], 1);
    atomicAdd(&g_efsum[d.w * 4 + 0], e3.x);
    atomicAdd(&g_efsum[d.w * 4 + 1], e3.y);
    atomicAdd(&g_efsum[d.w * 4 + 2], e3.z);
    atomicAdd(&g_efsum[d.w * 4 + 3], e3.w);
}

// ---------------- single-kernel exclusive scan (all blocks resident) ----------------
__global__ void scan_kernel() {
    __shared__ int s[256];
    int t = threadIdx.x;
    int b = blockIdx.x;
    int i = b * 256 + t;
    int v = (i < NN) ? g_count[i] : 0;
    s[t] = v;
    __syncthreads();
    for (int off = 1; off < 256; off <<= 1) {
        int add = (t >= off) ? s[t - off] : 0;
        __syncthreads();
        s[t] += add;
        __syncthreads();
    }
    int local_excl = s[t] - v;
    if (t == 255) {
        g_bsum[b] = s[255];
        __threadfence();
        atomicAdd(&g_scan_done, 1);
    }
    if (t == 0) {
        while (atomicAdd(&g_scan_done, 0) < NB_SCAN) { }
    }
    __syncthreads();
    int pre = 0;
    for (int k = t; k < b; k += 256) pre += g_bsum[k];
    s[t] = pre;
    __syncthreads();
    for (int o = 128; o; o >>= 1) {
        if (t < o) s[t] += s[t + o];
        __syncthreads();
    }
    if (i < NN) g_off[i] = s[0] + local_excl;
}

// ---------------- scatter: src ids only (4B random writes, L2-resident) ----------------
__global__ void scatter_kernel(const int4* __restrict__ src4,
                               const int4* __restrict__ dst4) {
    int i = blockIdx.x * blockDim.x + threadIdx.x;
    if (i >= NE / 4) return;
    int4 s = src4[i];
    int4 d = dst4[i];
    int p0 = g_off[d.x] + atomicAdd(&g_cursor[d.x], 1);
    g_srcs[p0] = s.x;
    int p1 = g_off[d.y] + atomicAdd(&g_cursor[d.y], 1);
    g_srcs[p1] = s.y;
    int p2 = g_off[d.z] + atomicAdd(&g_cursor[d.z], 1);
    g_srcs[p2] = s.z;
    int p3 = g_off[d.w] + atomicAdd(&g_cursor[d.w], 1);
    g_srcs[p3] = s.w;
}

// ---------------- layer 1: nf gather-reduce + MLP (warp per node) ----------------
__global__ void node1_kernel(const float* __restrict__ W1a, const float* __restrict__ b1a,
                             const float* __restrict__ W1b, const float* __restrict__ b1b) {
    __shared__ float sW1a[11 * 32];
    __shared__ float sW1b[32 * 32];
    __shared__ float sb1a[32];
    __shared__ float sb1b[32];
    int tid = threadIdx.x;
    for (int k = tid; k < 11 * 32; k += blockDim.x) sW1a[k] = W1a[k];
    for (int k = tid; k < 32 * 32; k += blockDim.x) sW1b[k] = W1b[k];
    if (tid < 32) { sb1a[tid] = b1a[tid]; sb1b[tid] = b1b[tid]; }
    __syncthreads();

    int warp = tid >> 5;
    int lane = tid & 31;
    int n = blockIdx.x * (blockDim.x >> 5) + warp;
    if (n >= NN) return;

    int start = g_off[n];
    int deg   = g_count[n];

    // sum node_feat[src] over incoming edges (L2-resident 32B gathers)
    float acc[7];
#pragma unroll
    for (int k = 0; k < 7; k++) acc[k] = 0.0f;

    const float4* nf4 = (const float4*)g_nf8;
    for (int j = lane; j < deg; j += 32) {
        int s = __ldg(&g_srcs[start + j]);     // sequential coalesced
        float4 a = __ldg(&nf4[s * 2]);         // L2-resident gather
        float4 b = __ldg(&nf4[s * 2 + 1]);
        acc[0] += a.x; acc[1] += a.y; acc[2] += a.z; acc[3] += a.w;
        acc[4] += b.x; acc[5] += b.y; acc[6] += b.z;
    }
#pragma unroll
    for (int off = 16; off; off >>= 1) {
#pragma unroll
        for (int k = 0; k < 7; k++)
            acc[k] += __shfl_xor_sync(0xffffffffu, acc[k], off);
    }

    float invd = 1.0f / fmaxf((float)deg, 1.0f);

    // edge-feature mean from the precomputed segment sums (uniform loads)
    float e0 = g_efsum[n * 4 + 0] * invd;
    float e1 = g_efsum[n * 4 + 1] * invd;
    float e2 = g_efsum[n * 4 + 2] * invd;
    float e3 = g_efsum[n * 4 + 3] * invd;

    float y = sb1a[lane];
    y = fmaf(e0, sW1a[0 * 32 + lane], y);
    y = fmaf(e1, sW1a[1 * 32 + lane], y);
    y = fmaf(e2, sW1a[2 * 32 + lane], y);
    y = fmaf(e3, sW1a[3 * 32 + lane], y);
#pragma unroll
    for (int k = 0; k < 7; k++)
        y = fmaf(acc[k] * invd, sW1a[(k + 4) * 32 + lane], y);
    y = fmaxf(y, 0.0f);

    float z = sb1b[lane];
#pragma unroll
    for (int k = 0; k < 32; k++) {
        float yk = __shfl_sync(0xffffffffu, y, k);
        z = fmaf(yk, sW1b[k * 32 + lane], z);
    }
    z = fmaxf(z, 0.0f);

    g_h1h[n * 32 + lane] = __float2half_rn(z);
}

// ---------------- layer 2: fp16 gather-reduce + MLP + pool (warp per node) ----------------
__global__ void node2_kernel(const float* __restrict__ W2a, const float* __restrict__ b2a,
                             const float* __restrict__ W2b, const float* __restrict__ b2b,
                             const int* __restrict__ graph_ids) {
    __shared__ float sW2a[32 * 32];
    __shared__ float sW2b[32 * 32];
    __shared__ float sb2a[32];
    __shared__ float sb2b[32];
    int tid = threadIdx.x;
    for (int k = tid; k < 32 * 32; k += blockDim.x) { sW2a[k] = W2a[k]; sW2b[k] = W2b[k]; }
    if (tid < 32) { sb2a[tid] = b2a[tid]; sb2b[tid] = b2b[tid]; }
    __syncthreads();

    int warp = tid >> 5;
    int lane = tid & 31;
    int n = blockIdx.x * (blockDim.x >> 5) + warp;
    if (n >= NN) return;

    int start = g_off[n];
    int deg   = g_count[n];

    float acc0 = 0.0f, acc1 = 0.0f, acc2 = 0.0f, acc3 = 0.0f;
    int j = 0;
    for (; j + 4 <= deg; j += 4) {
        int s0 = __ldg(&g_srcs[start + j + 0]);  // uniform broadcast
        int s1 = __ldg(&g_srcs[start + j + 1]);
        int s2 = __ldg(&g_srcs[start + j + 2]);
        int s3 = __ldg(&g_srcs[start + j + 3]);
        acc0 += __half2float(__ldg(&g_h1h[s0 * 32 + lane]));  // 64B coalesced L2 gathers
        acc1 += __half2float(__ldg(&g_h1h[s1 * 32 + lane]));
        acc2 += __half2float(__ldg(&g_h1h[s2 * 32 + lane]));
        acc3 += __half2float(__ldg(&g_h1h[s3 * 32 + lane]));
    }
    for (; j < deg; j++) {
        int s = __ldg(&g_srcs[start + j]);
        acc0 += __half2float(__ldg(&g_h1h[s * 32 + lane]));
    }
    float x = ((acc0 + acc1) + (acc2 + acc3)) / fmaxf((float)deg, 1.0f);

    float y = sb2a[lane];
#pragma unroll
    for (int k = 0; k < 32; k++) {
        float xk = __shfl_sync(0xffffffffu, x, k);
        y = fmaf(xk, sW2a[k * 32 + lane], y);
    }
    y = fmaxf(y, 0.0f);

    float z = sb2b[lane];
#pragma unroll
    for (int k = 0; k < 32; k++) {
        float yk = __shfl_sync(0xffffffffu, y, k);
        z = fmaf(yk, sW2b[k * 32 + lane], z);
    }
    z = fmaxf(z, 0.0f);  // >= 0 -> int-compare atomicMax is order-safe

    int g = graph_ids[n];
    atomicMax((int*)&g_pooled[g * 32 + lane], __float_as_int(z));
}

// ---------------- classifier head ----------------
__global__ void head_kernel(const float* __restrict__ Wm1, const float* __restrict__ bm1,
                            const float* __restrict__ Wm2, const float* __restrict__ bm2,
                            float* __restrict__ out) {
    int g = threadIdx.x;
    if (g >= NG) return;
    float p[32];
#pragma unroll
    for (int k = 0; k < 32; k++) p[k] = g_pooled[g * 32 + k];
    float hid[16];
#pragma unroll
    for (int jj = 0; jj < 16; jj++) {
        float a = bm1[jj];
#pragma unroll
        for (int k = 0; k < 32; k++) a = fmaf(p[k], Wm1[k * 16 + jj], a);
        hid[jj] = fmaxf(a, 0.0f);
    }
    float l0 = bm2[0], l1 = bm2[1];
#pragma unroll
    for (int jj = 0; jj < 16; jj++) {
        l0 = fmaf(hid[jj], Wm2[jj * 2 + 0], l0);
        l1 = fmaf(hid[jj], Wm2[jj * 2 + 1], l1);
    }
    float m = fmaxf(l0, l1);
    float e0 = expf(l0 - m);
    float e1 = expf(l1 - m);
    float inv = 1.0f / (e0 + e1);
    out[g * 2 + 0] = e0 * inv;
    out[g * 2 + 1] = e1 * inv;
}

extern "C" void kernel_launch(void* const* d_in, const int* in_sizes, int n_in,
                              void* d_out, int out_size) {
    const float* node_feat = (const float*)d_in[0];
    const float* edge_feat = (const float*)d_in[1];
    const int*   src       = (const int*)d_in[2];
    const int*   dst       = (const int*)d_in[3];
    const int*   graph_ids = (const int*)d_in[4];
    const float* W1a = (const float*)d_in[5];
    const float* b1a = (const float*)d_in[6];
    const float* W1b = (const float*)d_in[7];
    const float* b1b = (const float*)d_in[8];
    const float* W2a = (const float*)d_in[9];
    const float* b2a = (const float*)d_in[10];
    const float* W2b = (const float*)d_in[11];
    const float* b2b = (const float*)d_in[12];
    const float* Wm1 = (const float*)d_in[13];
    const float* bm1 = (const float*)d_in[14];
    const float* Wm2 = (const float*)d_in[15];
    const float* bm2 = (const float*)d_in[16];
    float* out = (float*)d_out;

    setup_kernel<<<(NN * 8 + 255) / 256, 256>>>(node_feat);
    histsum_kernel<<<(NE / 4 + 255) / 256, 256>>>((const int4*)dst, (const float4*)edge_feat);
    scan_kernel<<<NB_SCAN, 256>>>();
    scatter_kernel<<<(NE / 4 + 255) / 256, 256>>>((const int4*)src, (const int4*)dst);
    node1_kernel<<<NN / 8, 256>>>(W1a, b1a, W1b, b1b);
    node2_kernel<<<NN / 8, 256>>>(W2a, b2a, W2b, b2b, graph_ids);
    head_kernel<<<1, 64>>>(Wm1, bm1, Wm2, bm2, out);
}

// round 6
// speedup vs baseline: 1.0329x; 1.0329x over previous
#include <cuda_runtime.h>
#include <math.h>

#define NN 200000
#define NE 6400000
#define NG 64
#define NB_SCAN 782   // ceil(NN/256); all blocks resident (<=1184)

// ---- device scratch (static, no runtime allocation) ----
__device__ int    g_count[NN];       // in-degree
__device__ int    g_cursor[NN];      // scatter cursor
__device__ int    g_off[NN];         // CSR offsets (exclusive scan)
__device__ int    g_bsum[1024];      // scan block totals
__device__ int    g_sync1, g_sync2;  // global sync counters
__device__ int2   g_sorted[NE];      // (eid, src) sorted by dst
__device__ float  g_nf8[NN * 8];     // node_feat padded to 8 floats/row
__device__ float  g_h1[NN * 32];     // layer-1 output
__device__ float  g_pooled[NG * 32];

// ---------------- setup: zero scratch + pad node features ----------------
__global__ void setup_kernel(const float* __restrict__ node_feat) {
    int i = blockIdx.x * blockDim.x + threadIdx.x;
    if (i < NN * 8) {
        int n = i >> 3, k = i & 7;
        g_nf8[i] = (k < 7) ? node_feat[n * 7 + k] : 0.0f;
    }
    if (i < NN) { g_count[i] = 0; g_cursor[i] = 0; }
    if (i < NG * 32) g_pooled[i] = 0.0f;
    if (i == 0) { g_sync1 = 0; g_sync2 = 0; }
}

// ---------------- histogram of dst (4 edges per thread) ----------------
__global__ void hist_kernel(const int4* __restrict__ dst4) {
    int i = blockIdx.x * blockDim.x + threadIdx.x;
    if (i >= NE / 4) return;
    int4 d = dst4[i];
    atomicAdd(&g_count[d.x], 1);
    atomicAdd(&g_count[d.y], 1);
    atomicAdd(&g_count[d.z], 1);
    atomicAdd(&g_count[d.w], 1);
}

// ---------------- fused persistent scan + scatter ----------------
__global__ void scan_scatter_kernel(const int4* __restrict__ src4,
                                    const int4* __restrict__ dst4) {
    __shared__ int s[256];
    int t = threadIdx.x;
    int b = blockIdx.x;
    int i = b * 256 + t;

    // --- phase 1: block-local inclusive scan ---
    int v = (i < NN) ? g_count[i] : 0;
    s[t] = v;
    __syncthreads();
    for (int off = 1; off < 256; off <<= 1) {
        int add = (t >= off) ? s[t - off] : 0;
        __syncthreads();
        s[t] += add;
        __syncthreads();
    }
    int local_excl = s[t] - v;
    if (t == 255) {
        g_bsum[b] = s[255];
        __threadfence();
        atomicAdd(&g_sync1, 1);
    }
    if (t == 0) { while (atomicAdd(&g_sync1, 0) < NB_SCAN) { } }
    __syncthreads();

    // --- phase 2: block prefix from published totals ---
    int pre = 0;
    for (int k = t; k < b; k += 256) pre += g_bsum[k];
    s[t] = pre;
    __syncthreads();
    for (int o = 128; o; o >>= 1) {
        if (t < o) s[t] += s[t + o];
        __syncthreads();
    }
    if (i < NN) g_off[i] = s[0] + local_excl;

    // --- global sync: all offsets visible before any scatter ---
    __threadfence();
    __syncthreads();
    if (t == 0) {
        atomicAdd(&g_sync2, 1);
        while (atomicAdd(&g_sync2, 0) < NB_SCAN) { }
    }
    __syncthreads();

    // --- phase 3: grid-stride scatter of (eid, src) ---
    const int nquads = NE / 4;
    for (int q = b * 256 + t; q < nquads; q += NB_SCAN * 256) {
        int4 sv = src4[q];
        int4 dv = dst4[q];
        int e = q * 4;
        int p0 = g_off[dv.x] + atomicAdd(&g_cursor[dv.x], 1);
        g_sorted[p0] = make_int2(e + 0, sv.x);
        int p1 = g_off[dv.y] + atomicAdd(&g_cursor[dv.y], 1);
        g_sorted[p1] = make_int2(e + 1, sv.y);
        int p2 = g_off[dv.z] + atomicAdd(&g_cursor[dv.z], 1);
        g_sorted[p2] = make_int2(e + 2, sv.z);
        int p3 = g_off[dv.w] + atomicAdd(&g_cursor[dv.w], 1);
        g_sorted[p3] = make_int2(e + 3, sv.w);
    }
}

// ---------------- layer 1: gather-reduce + MLP (warp per node) ----------------
__global__ void node1_kernel(const float4* __restrict__ ef4,
                             const float* __restrict__ W1a, const float* __restrict__ b1a,
                             const float* __restrict__ W1b, const float* __restrict__ b1b) {
    __shared__ float sW1a[11 * 32];
    __shared__ float sW1b[32 * 32];
    __shared__ float sb1a[32];
    __shared__ float sb1b[32];
    int tid = threadIdx.x;
    for (int k = tid; k < 11 * 32; k += blockDim.x) sW1a[k] = W1a[k];
    for (int k = tid; k < 32 * 32; k += blockDim.x) sW1b[k] = W1b[k];
    if (tid < 32) { sb1a[tid] = b1a[tid]; sb1b[tid] = b1b[tid]; }
    __syncthreads();

    int warp = tid >> 5;
    int lane = tid & 31;
    int n = blockIdx.x * (blockDim.x >> 5) + warp;
    if (n >= NN) return;

    int start = g_off[n];
    int deg   = g_count[n];

    float acc[11];
#pragma unroll
    for (int k = 0; k < 11; k++) acc[k] = 0.0f;

    const float4* nf4 = (const float4*)g_nf8;
    for (int j = lane; j < deg; j += 32) {
        int2 p = g_sorted[start + j];        // sequential, coalesced
        float4 m = __ldg(&ef4[p.x]);         // random 16B gather
        acc[0] += m.x; acc[1] += m.y; acc[2] += m.z; acc[3] += m.w;
        float4 a = __ldg(&nf4[p.y * 2]);     // L2-resident 32B gather
        float4 b = __ldg(&nf4[p.y * 2 + 1]);
        acc[4] += a.x; acc[5] += a.y; acc[6] += a.z; acc[7] += a.w;
        acc[8] += b.x; acc[9] += b.y; acc[10] += b.z;
    }

#pragma unroll
    for (int off = 16; off; off >>= 1) {
#pragma unroll
        for (int k = 0; k < 11; k++)
            acc[k] += __shfl_xor_sync(0xffffffffu, acc[k], off);
    }

    float invd = 1.0f / fmaxf((float)deg, 1.0f);

    float y = sb1a[lane];
#pragma unroll
    for (int k = 0; k < 11; k++)
        y = fmaf(acc[k] * invd, sW1a[k * 32 + lane], y);
    y = fmaxf(y, 0.0f);

    float z = sb1b[lane];
#pragma unroll
    for (int k = 0; k < 32; k++) {
        float yk = __shfl_sync(0xffffffffu, y, k);
        z = fmaf(yk, sW1b[k * 32 + lane], z);
    }
    z = fmaxf(z, 0.0f);

    g_h1[n * 32 + lane] = z;
}

// ---------------- layer 2: deep-ILP gather-reduce + MLP + pool ----------------
__global__ void node2_kernel(const float* __restrict__ W2a, const float* __restrict__ b2a,
                             const float* __restrict__ W2b, const float* __restrict__ b2b,
                             const int* __restrict__ graph_ids) {
    __shared__ float sW2a[32 * 32];
    __shared__ float sW2b[32 * 32];
    __shared__ float sb2a[32];
    __shared__ float sb2b[32];
    int tid = threadIdx.x;
    for (int k = tid; k < 32 * 32; k += blockDim.x) { sW2a[k] = W2a[k]; sW2b[k] = W2b[k]; }
    if (tid < 32) { sb2a[tid] = b2a[tid]; sb2b[tid] = b2b[tid]; }
    __syncthreads();

    int warp = tid >> 5;
    int lane = tid & 31;
    int n = blockIdx.x * (blockDim.x >> 5) + warp;
    if (n >= NN) return;

    int start = g_off[n];
    int deg   = g_count[n];

    float acc0 = 0.0f, acc1 = 0.0f, acc2 = 0.0f, acc3 = 0.0f;
    int j = 0;
    // 8 independent gathers in flight: lanes 0-7 bulk-load the next 8 src ids,
    // shfl-broadcast, then issue 8 unordered LDGs.
    for (; j + 8 <= deg; j += 8) {
        int myidx = 0;
        if (lane < 8) myidx = g_sorted[start + j + lane].y;
        int s0 = __shfl_sync(0xffffffffu, myidx, 0);
        int s1 = __shfl_sync(0xffffffffu, myidx, 1);
        int s2 = __shfl_sync(0xffffffffu, myidx, 2);
        int s3 = __shfl_sync(0xffffffffu, myidx, 3);
        int s4 = __shfl_sync(0xffffffffu, myidx, 4);
        int s5 = __shfl_sync(0xffffffffu, myidx, 5);
        int s6 = __shfl_sync(0xffffffffu, myidx, 6);
        int s7 = __shfl_sync(0xffffffffu, myidx, 7);
        float v0 = __ldg(&g_h1[s0 * 32 + lane]);
        float v1 = __ldg(&g_h1[s1 * 32 + lane]);
        float v2 = __ldg(&g_h1[s2 * 32 + lane]);
        float v3 = __ldg(&g_h1[s3 * 32 + lane]);
        float v4 = __ldg(&g_h1[s4 * 32 + lane]);
        float v5 = __ldg(&g_h1[s5 * 32 + lane]);
        float v6 = __ldg(&g_h1[s6 * 32 + lane]);
        float v7 = __ldg(&g_h1[s7 * 32 + lane]);
        acc0 += v0 + v4;
        acc1 += v1 + v5;
        acc2 += v2 + v6;
        acc3 += v3 + v7;
    }
    for (; j < deg; j++) {
        int s = g_sorted[start + j].y;
        acc0 += __ldg(&g_h1[s * 32 + lane]);
    }
    float x = ((acc0 + acc1) + (acc2 + acc3)) / fmaxf((float)deg, 1.0f);

    float y = sb2a[lane];
#pragma unroll
    for (int k = 0; k < 32; k++) {
        float xk = __shfl_sync(0xffffffffu, x, k);
        y = fmaf(xk, sW2a[k * 32 + lane], y);
    }
    y = fmaxf(y, 0.0f);

    float z = sb2b[lane];
#pragma unroll
    for (int k = 0; k < 32; k++) {
        float yk = __shfl_sync(0xffffffffu, y, k);
        z = fmaf(yk, sW2b[k * 32 + lane], z);
    }
    z = fmaxf(z, 0.0f);  // >= 0 -> int-compare atomicMax is order-safe

    int g = graph_ids[n];
    atomicMax((int*)&g_pooled[g * 32 + lane], __float_as_int(z));
}

// ---------------- classifier head ----------------
__global__ void head_kernel(const float* __restrict__ Wm1, const float* __restrict__ bm1,
                            const float* __restrict__ Wm2, const float* __restrict__ bm2,
                            float* __restrict__ out) {
    int g = threadIdx.x;
    if (g >= NG) return;
    float p[32];
#pragma unroll
    for (int k = 0; k < 32; k++) p[k] = g_pooled[g * 32 + k];
    float hid[16];
#pragma unroll
    for (int jj = 0; jj < 16; jj++) {
        float a = bm1[jj];
#pragma unroll
        for (int k = 0; k < 32; k++) a = fmaf(p[k], Wm1[k * 16 + jj], a);
        hid[jj] = fmaxf(a, 0.0f);
    }
    float l0 = bm2[0], l1 = bm2[1];
#pragma unroll
    for (int jj = 0; jj < 16; jj++) {
        l0 = fmaf(hid[jj], Wm2[jj * 2 + 0], l0);
        l1 = fmaf(hid[jj], Wm2[jj * 2 + 1], l1);
    }
    float m = fmaxf(l0, l1);
    float e0 = expf(l0 - m);
    float e1 = expf(l1 - m);
    float inv = 1.0f / (e0 + e1);
    out[g * 2 + 0] = e0 * inv;
    out[g * 2 + 1] = e1 * inv;
}

extern "C" void kernel_launch(void* const* d_in, const int* in_sizes, int n_in,
                              void* d_out, int out_size) {
    const float* node_feat = (const float*)d_in[0];
    const float* edge_feat = (const float*)d_in[1];
    const int*   src       = (const int*)d_in[2];
    const int*   dst       = (const int*)d_in[3];
    const int*   graph_ids = (const int*)d_in[4];
    const float* W1a = (const float*)d_in[5];
    const float* b1a = (const float*)d_in[6];
    const float* W1b = (const float*)d_in[7];
    const float* b1b = (const float*)d_in[8];
    const float* W2a = (const float*)d_in[9];
    const float* b2a = (const float*)d_in[10];
    const float* W2b = (const float*)d_in[11];
    const float* b2b = (const float*)d_in[12];
    const float* Wm1 = (const float*)d_in[13];
    const float* bm1 = (const float*)d_in[14];
    const float* Wm2 = (const float*)d_in[15];
    const float* bm2 = (const float*)d_in[16];
    float* out = (float*)d_out;

    setup_kernel<<<(NN * 8 + 255) / 256, 256>>>(node_feat);
    hist_kernel<<<(NE / 4 + 255) / 256, 256>>>((const int4*)dst);
    scan_scatter_kernel<<<NB_SCAN, 256>>>((const int4*)src, (const int4*)dst);
    node1_kernel<<<NN / 8, 256>>>((const float4*)edge_feat, W1a, b1a, W1b, b1b);
    node2_kernel<<<NN / 8, 256>>>(W2a, b2a, W2b, b2b, graph_ids);
    head_kernel<<<1, 64>>>(Wm1, bm1, Wm2, bm2, out);
}

// round 8
// speedup vs baseline: 1.1095x; 1.0742x over previous
#include <cuda_runtime.h>
#include <cuda_fp16.h>
#include <stdint.h>
#include <math.h>

#define NN 200000
#define NE 6400000
#define NG 64
#define NB_SCAN 782   // ceil(NN/256); all blocks resident

// ---- device scratch (static, no runtime allocation) ----
__device__ int    g_count[NN];        // in-degree
__device__ int    g_cursor[NN];       // scatter cursor
__device__ int    g_off[NN];          // CSR offsets (exclusive scan)
__device__ int    g_bsum[1024];       // scan block totals
__device__ int    g_sync1, g_sync2;   // global sync counters
__device__ uint4  g_sorted[NE];       // {src, ef01(half2), ef23(half2), 0} sorted by dst
__device__ __half g_nfh[NN * 8];      // node_feat as half, padded to 8/row (16B)
__device__ __half g_h1h[NN * 32];     // layer-1 output (fp16, 12.8MB)
__device__ float  g_pooled[NG * 32];

// ---------------- setup: zero scratch + pad/convert node features ----------------
__global__ void setup_kernel(const float* __restrict__ node_feat) {
    int i = blockIdx.x * blockDim.x + threadIdx.x;
    if (i < NN * 8) {
        int n = i >> 3, k = i & 7;
        g_nfh[i] = __float2half_rn((k < 7) ? node_feat[n * 7 + k] : 0.0f);
    }
    if (i < NN) { g_count[i] = 0; g_cursor[i] = 0; }
    if (i < NG * 32) g_pooled[i] = 0.0f;
    if (i == 0) { g_sync1 = 0; g_sync2 = 0; }
}

// ---------------- histogram of dst (4 edges per thread) ----------------
__global__ void hist_kernel(const int4* __restrict__ dst4) {
    int i = blockIdx.x * blockDim.x + threadIdx.x;
    if (i >= NE / 4) return;
    int4 d = dst4[i];
    atomicAdd(&g_count[d.x], 1);
    atomicAdd(&g_count[d.y], 1);
    atomicAdd(&g_count[d.z], 1);
    atomicAdd(&g_count[d.w], 1);
}

__device__ __forceinline__ unsigned int pack_h2(float a, float b) {
    __half2 h = __floats2half2_rn(a, b);
    return *(unsigned int*)&h;
}

// ---------------- fused persistent scan + scatter (packs src + fp16 ef) ----------------
__global__ void scan_scatter_kernel(const int4* __restrict__ src4,
                                    const int4* __restrict__ dst4,
                                    const float4* __restrict__ ef4) {
    __shared__ int s[256];
    int t = threadIdx.x;
    int b = blockIdx.x;
    int i = b * 256 + t;

    // --- phase 1: block-local inclusive scan of degrees ---
    int v = (i < NN) ? g_count[i] : 0;
    s[t] = v;
    __syncthreads();
    for (int off = 1; off < 256; off <<= 1) {
        int add = (t >= off) ? s[t - off] : 0;
        __syncthreads();
        s[t] += add;
        __syncthreads();
    }
    int local_excl = s[t] - v;
    if (t == 255) {
        g_bsum[b] = s[255];
        __threadfence();
        atomicAdd(&g_sync1, 1);
    }
    if (t == 0) { while (atomicAdd(&g_sync1, 0) < NB_SCAN) { } }
    __syncthreads();

    // --- phase 2: block prefix from published totals ---
    int pre = 0;
    for (int k = t; k < b; k += 256) pre += g_bsum[k];
    s[t] = pre;
    __syncthreads();
    for (int o = 128; o; o >>= 1) {
        if (t < o) s[t] += s[t + o];
        __syncthreads();
    }
    if (i < NN) g_off[i] = s[0] + local_excl;

    // --- global sync before scatter ---
    __threadfence();
    __syncthreads();
    if (t == 0) {
        atomicAdd(&g_sync2, 1);
        while (atomicAdd(&g_sync2, 0) < NB_SCAN) { }
    }
    __syncthreads();

    // --- phase 3: grid-stride scatter of packed {src, fp16 edge_feat} ---
    const int nquads = NE / 4;
    for (int q = b * 256 + t; q < nquads; q += NB_SCAN * 256) {
        int4 sv = src4[q];
        int4 dv = dst4[q];
        float4 e0 = ef4[q * 4 + 0];
        float4 e1 = ef4[q * 4 + 1];
        float4 e2 = ef4[q * 4 + 2];
        float4 e3 = ef4[q * 4 + 3];
        uint4 w;
        w.w = 0u;

        int p0 = g_off[dv.x] + atomicAdd(&g_cursor[dv.x], 1);
        w.x = (unsigned int)sv.x; w.y = pack_h2(e0.x, e0.y); w.z = pack_h2(e0.z, e0.w);
        g_sorted[p0] = w;
        int p1 = g_off[dv.y] + atomicAdd(&g_cursor[dv.y], 1);
        w.x = (unsigned int)sv.y; w.y = pack_h2(e1.x, e1.y); w.z = pack_h2(e1.z, e1.w);
        g_sorted[p1] = w;
        int p2 = g_off[dv.z] + atomicAdd(&g_cursor[dv.z], 1);
        w.x = (unsigned int)sv.z; w.y = pack_h2(e2.x, e2.y); w.z = pack_h2(e2.z, e2.w);
        g_sorted[p2] = w;
        int p3 = g_off[dv.w] + atomicAdd(&g_cursor[dv.w], 1);
        w.x = (unsigned int)sv.w; w.y = pack_h2(e3.x, e3.y); w.z = pack_h2(e3.z, e3.w);
        g_sorted[p3] = w;
    }
}

// ---------------- layer 1: sequential edge stream + one fp16 nf gather ----------------
__global__ void node1_kernel(const float* __restrict__ W1a, const float* __restrict__ b1a,
                             const float* __restrict__ W1b, const float* __restrict__ b1b) {
    __shared__ float sW1a[11 * 32];
    __shared__ float sW1b[32 * 32];
    __shared__ float sb1a[32];
    __shared__ float sb1b[32];
    int tid = threadIdx.x;
    for (int k = tid; k < 11 * 32; k += blockDim.x) sW1a[k] = W1a[k];
    for (int k = tid; k < 32 * 32; k += blockDim.x) sW1b[k] = W1b[k];
    if (tid < 32) { sb1a[tid] = b1a[tid]; sb1b[tid] = b1b[tid]; }
    __syncthreads();

    int warp = tid >> 5;
    int lane = tid & 31;
    int n = blockIdx.x * (blockDim.x >> 5) + warp;
    if (n >= NN) return;

    int start = g_off[n];
    int deg   = g_count[n];

    float acc[11];
#pragma unroll
    for (int k = 0; k < 11; k++) acc[k] = 0.0f;

    const uint4* nfq = (const uint4*)g_nfh;
    for (int j = lane; j < deg; j += 32) {
        uint4 p = __ldg(&g_sorted[start + j]);   // coalesced 16B stream
        __half2 h01 = *(__half2*)&p.y;
        __half2 h23 = *(__half2*)&p.z;
        float2 e01 = __half22float2(h01);
        float2 e23 = __half22float2(h23);
        acc[0] += e01.x; acc[1] += e01.y; acc[2] += e23.x; acc[3] += e23.y;
        uint4 nf = __ldg(&nfq[p.x]);             // ONE 16B gather (L2/L1-resident)
        __half2 n0 = *(__half2*)&nf.x;
        __half2 n1 = *(__half2*)&nf.y;
        __half2 n2 = *(__half2*)&nf.z;
        __half2 n3 = *(__half2*)&nf.w;
        float2 f0 = __half22float2(n0);
        float2 f1 = __half22float2(n1);
        float2 f2 = __half22float2(n2);
        float2 f3 = __half22float2(n3);
        acc[4] += f0.x; acc[5] += f0.y;
        acc[6] += f1.x; acc[7] += f1.y;
        acc[8] += f2.x; acc[9] += f2.y;
        acc[10] += f3.x;
    }

#pragma unroll
    for (int off = 16; off; off >>= 1) {
#pragma unroll
        for (int k = 0; k < 11; k++)
            acc[k] += __shfl_xor_sync(0xffffffffu, acc[k], off);
    }

    float invd = 1.0f / fmaxf((float)deg, 1.0f);

    float y = sb1a[lane];
#pragma unroll
    for (int k = 0; k < 11; k++)
        y = fmaf(acc[k] * invd, sW1a[k * 32 + lane], y);
    y = fmaxf(y, 0.0f);

    float z = sb1b[lane];
#pragma unroll
    for (int k = 0; k < 32; k++) {
        float yk = __shfl_sync(0xffffffffu, y, k);
        z = fmaf(yk, sW1b[k * 32 + lane], z);
    }
    z = fmaxf(z, 0.0f);

    g_h1h[n * 32 + lane] = __float2half_rn(z);
}

// ---------------- layer 2: deep-ILP fp16 gather-reduce + MLP + pool ----------------
__global__ void node2_kernel(const float* __restrict__ W2a, const float* __restrict__ b2a,
                             const float* __restrict__ W2b, const float* __restrict__ b2b,
                             const int* __restrict__ graph_ids) {
    __shared__ float sW2a[32 * 32];
    __shared__ float sW2b[32 * 32];
    __shared__ float sb2a[32];
    __shared__ float sb2b[32];
    int tid = threadIdx.x;
    for (int k = tid; k < 32 * 32; k += blockDim.x) { sW2a[k] = W2a[k]; sW2b[k] = W2b[k]; }
    if (tid < 32) { sb2a[tid] = b2a[tid]; sb2b[tid] = b2b[tid]; }
    __syncthreads();

    int warp = tid >> 5;
    int lane = tid & 31;
    int n = blockIdx.x * (blockDim.x >> 5) + warp;
    if (n >= NN) return;

    int start = g_off[n];
    int deg   = g_count[n];

    float acc0 = 0.0f, acc1 = 0.0f, acc2 = 0.0f, acc3 = 0.0f;
    int j = 0;
    // 8 independent gathers in flight: lanes 0-7 load the next 8 entries' src.
    for (; j + 8 <= deg; j += 8) {
        int myidx = 0;
        if (lane < 8) myidx = (int)g_sorted[start + j + lane].x;
        int s0 = __shfl_sync(0xffffffffu, myidx, 0);
        int s1 = __shfl_sync(0xffffffffu, myidx, 1);
        int s2 = __shfl_sync(0xffffffffu, myidx, 2);
        int s3 = __shfl_sync(0xffffffffu, myidx, 3);
        int s4 = __shfl_sync(0xffffffffu, myidx, 4);
        int s5 = __shfl_sync(0xffffffffu, myidx, 5);
        int s6 = __shfl_sync(0xffffffffu, myidx, 6);
        int s7 = __shfl_sync(0xffffffffu, myidx, 7);
        float v0 = __half2float(__ldg(&g_h1h[s0 * 32 + lane]));
        float v1 = __half2float(__ldg(&g_h1h[s1 * 32 + lane]));
        float v2 = __half2float(__ldg(&g_h1h[s2 * 32 + lane]));
        float v3 = __half2float(__ldg(&g_h1h[s3 * 32 + lane]));
        float v4 = __half2float(__ldg(&g_h1h[s4 * 32 + lane]));
        float v5 = __half2float(__ldg(&g_h1h[s5 * 32 + lane]));
        float v6 = __half2float(__ldg(&g_h1h[s6 * 32 + lane]));
        float v7 = __half2float(__ldg(&g_h1h[s7 * 32 + lane]));
        acc0 += v0 + v4;
        acc1 += v1 + v5;
        acc2 += v2 + v6;
        acc3 += v3 + v7;
    }
    for (; j < deg; j++) {
        int s = (int)g_sorted[start + j].x;
        acc0 += __half2float(__ldg(&g_h1h[s * 32 + lane]));
    }
    float x = ((acc0 + acc1) + (acc2 + acc3)) / fmaxf((float)deg, 1.0f);

    float y = sb2a[lane];
#pragma unroll
    for (int k = 0; k < 32; k++) {
        float xk = __shfl_sync(0xffffffffu, x, k);
        y = fmaf(xk, sW2a[k * 32 + lane], y);
    }
    y = fmaxf(y, 0.0f);

    float z = sb2b[lane];
#pragma unroll
    for (int k = 0; k < 32; k++) {
        float yk = __shfl_sync(0xffffffffu, y, k);
        z = fmaf(yk, sW2b[k * 32 + lane], z);
    }
    z = fmaxf(z, 0.0f);  // >= 0 -> int-compare atomicMax is order-safe

    int g = graph_ids[n];
    atomicMax((int*)&g_pooled[g * 32 + lane], __float_as_int(z));
}

// ---------------- classifier head ----------------
__global__ void head_kernel(const float* __restrict__ Wm1, const float* __restrict__ bm1,
                            const float* __restrict__ Wm2, const float* __restrict__ bm2,
                            float* __restrict__ out) {
    int g = threadIdx.x;
    if (g >= NG) return;
    float p[32];
#pragma unroll
    for (int k = 0; k < 32; k++) p[k] = g_pooled[g * 32 + k];
    float hid[16];
#pragma unroll
    for (int jj = 0; jj < 16; jj++) {
        float a = bm1[jj];
#pragma unroll
        for (int k = 0; k < 32; k++) a = fmaf(p[k], Wm1[k * 16 + jj], a);
        hid[jj] = fmaxf(a, 0.0f);
    }
    float l0 = bm2[0], l1 = bm2[1];
#pragma unroll
    for (int jj = 0; jj < 16; jj++) {
        l0 = fmaf(hid[jj], Wm2[jj * 2 + 0], l0);
        l1 = fmaf(hid[jj], Wm2[jj * 2 + 1], l1);
    }
    float m = fmaxf(l0, l1);
    float e0 = expf(l0 - m);
    float e1 = expf(l1 - m);
    float inv = 1.0f / (e0 + e1);
    out[g * 2 + 0] = e0 * inv;
    out[g * 2 + 1] = e1 * inv;
}

extern "C" void kernel_launch(void* const* d_in, const int* in_sizes, int n_in,
                              void* d_out, int out_size) {
    const float* node_feat = (const float*)d_in[0];
    const float* edge_feat = (const float*)d_in[1];
    const int*   src       = (const int*)d_in[2];
    const int*   dst       = (const int*)d_in[3];
    const int*   graph_ids = (const int*)d_in[4];
    const float* W1a = (const float*)d_in[5];
    const float* b1a = (const float*)d_in[6];
    const float* W1b = (const float*)d_in[7];
    const float* b1b = (const float*)d_in[8];
    const float* W2a = (const float*)d_in[9];
    const float* b2a = (const float*)d_in[10];
    const float* W2b = (const float*)d_in[11];
    const float* b2b = (const float*)d_in[12];
    const float* Wm1 = (const float*)d_in[13];
    const float* bm1 = (const float*)d_in[14];
    const float* Wm2 = (const float*)d_in[15];
    const float* bm2 = (const float*)d_in[16];
    float* out = (float*)d_out;

    setup_kernel<<<(NN * 8 + 255) / 256, 256>>>(node_feat);
    hist_kernel<<<(NE / 4 + 255) / 256, 256>>>((const int4*)dst);
    scan_scatter_kernel<<<NB_SCAN, 256>>>((const int4*)src, (const int4*)dst,
                                          (const float4*)edge_feat);
    node1_kernel<<<NN / 8, 256>>>(W1a, b1a, W1b, b1b);
    node2_kernel<<<NN / 8, 256>>>(W2a, b2a, W2b, b2b, graph_ids);
    head_kernel<<<1, 64>>>(Wm1, bm1, Wm2, bm2, out);
}